// round 2
// baseline (speedup 1.0000x reference)
#include <cuda_runtime.h>
#include <cstdint>

#define NN      50000
#define E_RSR   3000000
#define E_RTR   1000000
#define E_RUR   200000
#define E_TOT   (E_RSR + E_RTR + E_RUR)

// ---------------- device scratch ----------------
__device__ float g_rinv_out[3 * NN];
__device__ float g_rinv_in [3 * NN];
__device__ float g_hr[3][NN * 16];
__device__ float g_acc1[NN * 16];
__device__ float g_gv[3 * NN];
__device__ int   g_src32[E_TOT];
__device__ int   g_dst32[E_TOT];
__device__ int   g_is64;

// ---------------- helpers ----------------
__device__ __forceinline__ void red_add_v4(float* p, float a, float b, float c, float d) {
    asm volatile("red.global.add.v4.f32 [%0], {%1, %2, %3, %4};"
                 :: "l"(p), "f"(a), "f"(b), "f"(c), "f"(d) : "memory");
}
__device__ __forceinline__ int ldcs_i(const int* p) {
    int v; asm volatile("ld.global.cs.b32 %0, [%1];" : "=r"(v) : "l"(p)); return v;
}
__device__ __forceinline__ void stcs_i(int* p, int v) {
    asm volatile("st.global.cs.b32 [%0], %1;" :: "l"(p), "r"(v) : "memory");
}
__device__ __forceinline__ int4 ldcs_i4(const int4* p) {
    int4 v;
    asm volatile("ld.global.cs.v4.b32 {%0,%1,%2,%3}, [%4];"
                 : "=r"(v.x), "=r"(v.y), "=r"(v.z), "=r"(v.w) : "l"(p));
    return v;
}
__device__ __forceinline__ int2 ldcs_i2(const int2* p) {
    int2 v;
    asm volatile("ld.global.cs.v2.b32 {%0,%1}, [%2];" : "=r"(v.x), "=r"(v.y) : "l"(p));
    return v;
}

// ---------------- dtype probe ----------------
__global__ void k_probe(const unsigned* p) {
    if (threadIdx.x == 0) {
        int all0 = 1;
        #pragma unroll 1
        for (int k = 0; k < 64; k++)
            if (p[2 * k + 1] != 0u) { all0 = 0; break; }
        g_is64 = all0;
    }
}

// ---------------- zero scratch + init out with summed layer-2 bias ----------------
__global__ void k_init(float* out, const float* __restrict__ b2) {
    int i = blockIdx.x * blockDim.x + threadIdx.x;
    int stride = gridDim.x * blockDim.x;
    for (int j = i; j < NN * 16; j += stride) g_acc1[j] = 0.f;
    for (int j = i; j < 3 * NN; j += stride) { g_rinv_out[j] = 0.f; g_rinv_in[j] = 0.f; }
    float b2s = b2[0] + b2[1] + b2[2];
    for (int j = i; j < NN; j += stride) out[j] = b2s;
}

// ---------------- convert to int32 + count degrees (2 edges/thread) ----------------
__global__ void k_convert(const void* s0, const void* d0,
                          const void* s1, const void* d1,
                          const void* s2, const void* d2) {
    int t = blockIdx.x * blockDim.x + threadIdx.x;   // pair index
    int i = t * 2;                                    // first edge global index
    if (i >= E_TOT) return;
    int r, e, n;
    const void *sp, *dp;
    if (i < E_RSR)                { r = 0; e = i;                 sp = s0; dp = d0; n = E_RSR; }
    else if (i < E_RSR + E_RTR)   { r = 1; e = i - E_RSR;         sp = s1; dp = d1; n = E_RTR; }
    else                          { r = 2; e = i - E_RSR - E_RTR; sp = s2; dp = d2; n = E_RUR; }
    int cnt = (e + 1 < n) ? 2 : 1;   // relation sizes are even; a pair never straddles relations

    int sA, sB, dA, dB;
    if (g_is64) {
        if (cnt == 2) {
            int4 sv = ldcs_i4((const int4*)((const char*)sp + (size_t)e * 8));
            int4 dv = ldcs_i4((const int4*)((const char*)dp + (size_t)e * 8));
            sA = sv.x; sB = sv.z; dA = dv.x; dB = dv.z;
        } else {
            sA = (int)((const long long*)sp)[e]; sB = 0;
            dA = (int)((const long long*)dp)[e]; dB = 0;
        }
    } else {
        if (cnt == 2) {
            int2 sv = ldcs_i2((const int2*)((const char*)sp + (size_t)e * 4));
            int2 dv = ldcs_i2((const int2*)((const char*)dp + (size_t)e * 4));
            sA = sv.x; sB = sv.y; dA = dv.x; dB = dv.y;
        } else {
            sA = ((const int*)sp)[e]; sB = 0;
            dA = ((const int*)dp)[e]; dB = 0;
        }
    }
    stcs_i(&g_src32[i], sA);
    stcs_i(&g_dst32[i], dA);
    atomicAdd(&g_rinv_out[r * NN + sA], 1.f);
    atomicAdd(&g_rinv_in [r * NN + dA], 1.f);
    if (cnt == 2) {
        stcs_i(&g_src32[i + 1], sB);
        stcs_i(&g_dst32[i + 1], dB);
        atomicAdd(&g_rinv_out[r * NN + sB], 1.f);
        atomicAdd(&g_rinv_in [r * NN + dB], 1.f);
    }
}

// ---------------- deg -> rsqrt(max(deg,1)) ----------------
__global__ void k_findeg() {
    int i = blockIdx.x * blockDim.x + threadIdx.x;
    if (i >= 3 * NN) return;
    g_rinv_out[i] = rsqrtf(fmaxf(g_rinv_out[i], 1.f));
    g_rinv_in[i]  = rsqrtf(fmaxf(g_rinv_in[i],  1.f));
}

// ---------------- layer-1 transform ----------------
__global__ void k_transform1(const float* __restrict__ x, const float* __restrict__ W1) {
    __shared__ float sW[3 * 32 * 16];
    for (int j = threadIdx.x; j < 1536; j += blockDim.x) sW[j] = W1[j];
    __syncthreads();
    int n = blockIdx.x * blockDim.x + threadIdx.x;
    if (n >= NN) return;
    float xv[32];
    const float4* xp = (const float4*)(x + (size_t)n * 32);
    #pragma unroll
    for (int q = 0; q < 8; q++) {
        float4 v = xp[q];
        xv[4 * q + 0] = v.x; xv[4 * q + 1] = v.y; xv[4 * q + 2] = v.z; xv[4 * q + 3] = v.w;
    }
    #pragma unroll
    for (int r = 0; r < 3; r++) {
        float rv = g_rinv_out[r * NN + n];
        float o[16];
        #pragma unroll
        for (int j = 0; j < 16; j++) o[j] = 0.f;
        #pragma unroll
        for (int k = 0; k < 32; k++) {
            float xk = xv[k];
            const float* w = &sW[r * 512 + k * 16];
            #pragma unroll
            for (int j = 0; j < 16; j++) o[j] = fmaf(xk, w[j], o[j]);
        }
        float4* hp = (float4*)&g_hr[r][n * 16];
        #pragma unroll
        for (int q = 0; q < 4; q++) {
            float4 v;
            v.x = o[4 * q + 0] * rv; v.y = o[4 * q + 1] * rv;
            v.z = o[4 * q + 2] * rv; v.w = o[4 * q + 3] * rv;
            hp[q] = v;
        }
    }
}

// ---------------- layer-1 SpMM: one thread per edge, all relations ----------------
__global__ void __launch_bounds__(256) k_spmm1_all() {
    int e = blockIdx.x * blockDim.x + threadIdx.x;
    if (e >= E_TOT) return;
    int r = (e >= E_RSR) + (e >= E_RSR + E_RTR);
    int s = ldcs_i(&g_src32[e]);
    int d = ldcs_i(&g_dst32[e]);
    float w = __ldg(&g_rinv_in[r * NN + d]);
    const float4* hp = (const float4*)&g_hr[r][s * 16];
    float* ap = &g_acc1[d * 16];
    float4 v0 = hp[0], v1 = hp[1], v2 = hp[2], v3 = hp[3];
    red_add_v4(ap +  0, v0.x * w, v0.y * w, v0.z * w, v0.w * w);
    red_add_v4(ap +  4, v1.x * w, v1.y * w, v1.z * w, v1.w * w);
    red_add_v4(ap +  8, v2.x * w, v2.y * w, v2.z * w, v2.w * w);
    red_add_v4(ap + 12, v3.x * w, v3.y * w, v3.z * w, v3.w * w);
}

// ---------------- relu + bias + layer-2 projection ----------------
__global__ void k_relu_g(const float* __restrict__ b1, const float* __restrict__ W2) {
    int n = blockIdx.x * blockDim.x + threadIdx.x;
    if (n >= NN) return;
    float h[16];
    const float4* ap = (const float4*)&g_acc1[n * 16];
    #pragma unroll
    for (int q = 0; q < 4; q++) {
        float4 v = ap[q];
        h[4 * q + 0] = v.x; h[4 * q + 1] = v.y; h[4 * q + 2] = v.z; h[4 * q + 3] = v.w;
    }
    #pragma unroll
    for (int k = 0; k < 16; k++) {
        float bsum = __ldg(&b1[k]) + __ldg(&b1[16 + k]) + __ldg(&b1[32 + k]);
        h[k] = fmaxf(h[k] + bsum, 0.f);
    }
    #pragma unroll
    for (int r = 0; r < 3; r++) {
        float acc = 0.f;
        #pragma unroll
        for (int k = 0; k < 16; k++) acc = fmaf(h[k], __ldg(&W2[r * 16 + k]), acc);
        g_gv[r * NN + n] = acc * g_rinv_out[r * NN + n];
    }
}

// ---------------- layer-2 scalar SpMM: one merged launch ----------------
__global__ void __launch_bounds__(256) k_spmm2_all(float* __restrict__ out) {
    int e = blockIdx.x * blockDim.x + threadIdx.x;
    if (e >= E_TOT) return;
    int r = (e >= E_RSR) + (e >= E_RSR + E_RTR);
    int s = ldcs_i(&g_src32[e]);
    int d = ldcs_i(&g_dst32[e]);
    atomicAdd(&out[d], g_gv[r * NN + s] * __ldg(&g_rinv_in[r * NN + d]));
}

// =====================================================================================
extern "C" void kernel_launch(void* const* d_in, const int* in_sizes, int n_in,
                              void* d_out, int out_size) {
    const float* x  = (const float*)d_in[0];
    const void*  s0 = d_in[1]; const void* d0 = d_in[2];
    const void*  s1 = d_in[3]; const void* d1 = d_in[4];
    const void*  s2 = d_in[5]; const void* d2 = d_in[6];
    const float* W1 = (const float*)d_in[7];
    const float* b1 = (const float*)d_in[8];
    const float* W2 = (const float*)d_in[9];
    const float* b2 = (const float*)d_in[10];
    float* out = (float*)d_out;

    k_probe<<<1, 32>>>((const unsigned*)s0);
    k_init<<<1024, 256>>>(out, b2);
    k_convert<<<(E_TOT / 2 + 255) / 256, 256>>>(s0, d0, s1, d1, s2, d2);
    k_findeg<<<(3 * NN + 255) / 256, 256>>>();
    k_transform1<<<(NN + 127) / 128, 128>>>(x, W1);
    k_spmm1_all<<<(E_TOT + 255) / 256, 256>>>();
    k_relu_g<<<(NN + 127) / 128, 128>>>(b1, W2);
    k_spmm2_all<<<(E_TOT + 255) / 256, 256>>>(out);
}

// round 3
// speedup vs baseline: 1.3602x; 1.3602x over previous
#include <cuda_runtime.h>
#include <cstdint>

#define NN      50000
#define E_RSR   3000000
#define E_RTR   1000000
#define E_RUR   200000
#define E_TOT   4200000
#define NROWS   (3 * NN)
#define NB_SCAN 147            // ceil(150000 / 1024)

// ---------------- device scratch ----------------
__device__ int   g_deg_in [NROWS];
__device__ int   g_deg_out[NROWS];
__device__ float g_rinv_in [NROWS];
__device__ float g_rinv_out[NROWS];
__device__ int   g_rowptr[NROWS];
__device__ int   g_cursor[NROWS];
__device__ int   g_bsum[256];
__device__ int   g_src32[E_TOT];
__device__ int   g_dst32[E_TOT];
__device__ int   g_ssrc [E_TOT];       // src indices sorted by (relation, dst)
__device__ float g_hr[3][NN * 16];
__device__ float g_gv[NROWS];
__device__ int   g_is64;

// ---------------- helpers ----------------
__device__ __forceinline__ int4 ldcs_i4(const int4* p) {
    int4 v;
    asm volatile("ld.global.cs.v4.b32 {%0,%1,%2,%3}, [%4];"
                 : "=r"(v.x), "=r"(v.y), "=r"(v.z), "=r"(v.w) : "l"(p));
    return v;
}
__device__ __forceinline__ int2 ldcs_i2(const int2* p) {
    int2 v;
    asm volatile("ld.global.cs.v2.b32 {%0,%1}, [%2];" : "=r"(v.x), "=r"(v.y) : "l"(p));
    return v;
}

// ---------------- init: zero degree counters + dtype probe ----------------
__global__ void k_init(const unsigned* p) {
    int i = blockIdx.x * blockDim.x + threadIdx.x;
    if (i == 0) {
        int all0 = 1;
        #pragma unroll 1
        for (int k = 0; k < 64; k++)
            if (p[2 * k + 1] != 0u) { all0 = 0; break; }
        g_is64 = all0;
    }
    if (i < NROWS) { g_deg_in[i] = 0; g_deg_out[i] = 0; }
}

// ---------------- convert to int32 + count degrees (2 edges/thread) ----------------
__global__ void k_count(const void* s0, const void* d0,
                        const void* s1, const void* d1,
                        const void* s2, const void* d2) {
    int t = blockIdx.x * blockDim.x + threadIdx.x;
    int i = t * 2;
    if (i >= E_TOT) return;
    int r, e;
    const void *sp, *dp;
    if (i < E_RSR)                { r = 0; e = i;                 sp = s0; dp = d0; }
    else if (i < E_RSR + E_RTR)   { r = 1; e = i - E_RSR;         sp = s1; dp = d1; }
    else                          { r = 2; e = i - E_RSR - E_RTR; sp = s2; dp = d2; }
    // all relation sizes are even -> a pair never straddles a relation boundary
    int sA, sB, dA, dB;
    if (g_is64) {
        int4 sv = ldcs_i4((const int4*)((const char*)sp + (size_t)e * 8));
        int4 dv = ldcs_i4((const int4*)((const char*)dp + (size_t)e * 8));
        sA = sv.x; sB = sv.z; dA = dv.x; dB = dv.z;
    } else {
        int2 sv = ldcs_i2((const int2*)((const char*)sp + (size_t)e * 4));
        int2 dv = ldcs_i2((const int2*)((const char*)dp + (size_t)e * 4));
        sA = sv.x; sB = sv.y; dA = dv.x; dB = dv.y;
    }
    *(int2*)&g_src32[i] = make_int2(sA, sB);
    *(int2*)&g_dst32[i] = make_int2(dA, dB);
    int rb = r * NN;
    atomicAdd(&g_deg_out[rb + sA], 1);
    atomicAdd(&g_deg_out[rb + sB], 1);
    atomicAdd(&g_deg_in [rb + dA], 1);
    atomicAdd(&g_deg_in [rb + dB], 1);
}

// ---------------- scan stage 1: per-block (1024 elems) scan + rinv ----------------
__global__ void k_scan1() {
    __shared__ int sd[256];
    int t = threadIdx.x;
    int base = blockIdx.x * 1024 + t * 4;
    int v[4]; int s = 0;
    #pragma unroll
    for (int k = 0; k < 4; k++) {
        int idx = base + k;
        int dv = (idx < NROWS) ? g_deg_in[idx] : 0;
        v[k] = dv; s += dv;
        if (idx < NROWS) {
            g_rinv_in [idx] = rsqrtf(fmaxf((float)dv, 1.f));
            g_rinv_out[idx] = rsqrtf(fmaxf((float)g_deg_out[idx], 1.f));
        }
    }
    sd[t] = s;
    __syncthreads();
    for (int off = 1; off < 256; off <<= 1) {
        int y = (t >= off) ? sd[t - off] : 0;
        int x = sd[t];
        __syncthreads();
        sd[t] = x + y;
        __syncthreads();
    }
    int excl = sd[t] - s;   // exclusive prefix of this thread's 4-group within block
    int run = excl;
    #pragma unroll
    for (int k = 0; k < 4; k++) {
        int idx = base + k;
        if (idx < NROWS) g_rowptr[idx] = run;
        run += v[k];
    }
    if (t == 255) g_bsum[blockIdx.x] = sd[255];
}

// ---------------- scan stage 2: exclusive scan of block sums ----------------
__global__ void k_scan2() {
    __shared__ int sd[256];
    int t = threadIdx.x;
    int v = (t < NB_SCAN) ? g_bsum[t] : 0;
    sd[t] = v;
    __syncthreads();
    for (int off = 1; off < 256; off <<= 1) {
        int y = (t >= off) ? sd[t - off] : 0;
        int x = sd[t];
        __syncthreads();
        sd[t] = x + y;
        __syncthreads();
    }
    if (t < NB_SCAN) g_bsum[t] = sd[t] - v;
}

// ---------------- scan stage 3: add block offsets, init cursors ----------------
__global__ void k_scan3() {
    int i = blockIdx.x * blockDim.x + threadIdx.x;
    if (i >= NROWS) return;
    int val = g_rowptr[i] + g_bsum[i >> 10];
    g_rowptr[i] = val;
    g_cursor[i] = val;
}

// ---------------- scatter: counting-sort edges by (relation, dst) ----------------
__global__ void __launch_bounds__(256) k_scatter() {
    int i = blockIdx.x * blockDim.x + threadIdx.x;
    if (i >= E_TOT) return;
    int r = (i >= E_RSR) + (i >= E_RSR + E_RTR);
    int s = g_src32[i];
    int d = g_dst32[i];
    int pos = atomicAdd(&g_cursor[r * NN + d], 1);
    g_ssrc[pos] = s;
}

// ---------------- layer-1 transform: hr[r][n] = (x[n]*rinv_out[r][n]) @ W1[r] ----------------
__global__ void k_transform1(const float* __restrict__ x, const float* __restrict__ W1) {
    __shared__ float sW[3 * 32 * 16];
    for (int j = threadIdx.x; j < 1536; j += blockDim.x) sW[j] = W1[j];
    __syncthreads();
    int n = blockIdx.x * blockDim.x + threadIdx.x;
    if (n >= NN) return;
    float xv[32];
    const float4* xp = (const float4*)(x + (size_t)n * 32);
    #pragma unroll
    for (int q = 0; q < 8; q++) {
        float4 v = xp[q];
        xv[4 * q + 0] = v.x; xv[4 * q + 1] = v.y; xv[4 * q + 2] = v.z; xv[4 * q + 3] = v.w;
    }
    #pragma unroll
    for (int r = 0; r < 3; r++) {
        float rv = g_rinv_out[r * NN + n];
        float o[16];
        #pragma unroll
        for (int j = 0; j < 16; j++) o[j] = 0.f;
        #pragma unroll
        for (int k = 0; k < 32; k++) {
            float xk = xv[k];
            const float* w = &sW[r * 512 + k * 16];
            #pragma unroll
            for (int j = 0; j < 16; j++) o[j] = fmaf(xk, w[j], o[j]);
        }
        float4* hp = (float4*)&g_hr[r][n * 16];
        #pragma unroll
        for (int q = 0; q < 4; q++) {
            float4 v;
            v.x = o[4 * q + 0] * rv; v.y = o[4 * q + 1] * rv;
            v.z = o[4 * q + 2] * rv; v.w = o[4 * q + 3] * rv;
            hp[q] = v;
        }
    }
}

// ---------------- gather layer 1 (fused relu + bias + W2 projection) ----------------
// one warp per dst node; lane = slot*4 + chunk; 8 edges x 4 feature-chunks / iter
__global__ void __launch_bounds__(256) k_gather1(const float* __restrict__ b1,
                                                 const float* __restrict__ W2) {
    int wid = (blockIdx.x * blockDim.x + threadIdx.x) >> 5;
    if (wid >= NN) return;
    int lane = threadIdx.x & 31;
    int slot = lane >> 2, chunk = lane & 3;
    float4 acc = make_float4(0.f, 0.f, 0.f, 0.f);
    #pragma unroll
    for (int r = 0; r < 3; r++) {
        int j = r * NN + wid;
        int start = g_rowptr[j];
        int end = (j == NROWS - 1) ? E_TOT : g_rowptr[j + 1];
        float w = g_rinv_in[j];
        for (int base = start; base < end; base += 8) {
            int eid = base + slot;
            if (eid < end) {
                int s = __ldg(&g_ssrc[eid]);
                float4 v = *(const float4*)&g_hr[r][s * 16 + chunk * 4];
                acc.x = fmaf(v.x, w, acc.x);
                acc.y = fmaf(v.y, w, acc.y);
                acc.z = fmaf(v.z, w, acc.z);
                acc.w = fmaf(v.w, w, acc.w);
            }
        }
    }
    // reduce across the 8 slots (keep chunk)
    #pragma unroll
    for (int m = 16; m >= 4; m >>= 1) {
        acc.x += __shfl_xor_sync(0xffffffffu, acc.x, m);
        acc.y += __shfl_xor_sync(0xffffffffu, acc.y, m);
        acc.z += __shfl_xor_sync(0xffffffffu, acc.z, m);
        acc.w += __shfl_xor_sync(0xffffffffu, acc.w, m);
    }
    // bias (summed over relations) + relu; element indices chunk*4 .. chunk*4+3
    int c4 = chunk * 4;
    #pragma unroll
    for (int k = 0; k < 4; k++) {
        float bs = __ldg(&b1[c4 + k]) + __ldg(&b1[16 + c4 + k]) + __ldg(&b1[32 + c4 + k]);
        float* a = (k == 0) ? &acc.x : (k == 1) ? &acc.y : (k == 2) ? &acc.z : &acc.w;
        *a = fmaxf(*a + bs, 0.f);
    }
    // layer-2 projection per relation: dot(h, W2[r]) * rinv_out[r]
    #pragma unroll
    for (int r = 0; r < 3; r++) {
        const float* w2 = W2 + r * 16 + c4;
        float p = acc.x * __ldg(&w2[0]) + acc.y * __ldg(&w2[1])
                + acc.z * __ldg(&w2[2]) + acc.w * __ldg(&w2[3]);
        p += __shfl_xor_sync(0xffffffffu, p, 1);
        p += __shfl_xor_sync(0xffffffffu, p, 2);
        if (lane == r) g_gv[r * NN + wid] = p * g_rinv_out[r * NN + wid];
    }
}

// ---------------- gather layer 2: out[dst] = sum_r sum_e gv[r][src]*rinv_in + b2s ----------------
__global__ void __launch_bounds__(256) k_gather2(float* __restrict__ out,
                                                 const float* __restrict__ b2) {
    int wid = (blockIdx.x * blockDim.x + threadIdx.x) >> 5;
    if (wid >= NN) return;
    int lane = threadIdx.x & 31;
    float sum = 0.f;
    #pragma unroll
    for (int r = 0; r < 3; r++) {
        int j = r * NN + wid;
        int start = g_rowptr[j];
        int end = (j == NROWS - 1) ? E_TOT : g_rowptr[j + 1];
        float w = g_rinv_in[j];
        for (int base = start; base < end; base += 32) {
            int eid = base + lane;
            if (eid < end) {
                int s = __ldg(&g_ssrc[eid]);
                sum = fmaf(__ldg(&g_gv[r * NN + s]), w, sum);
            }
        }
    }
    #pragma unroll
    for (int m = 16; m >= 1; m >>= 1)
        sum += __shfl_xor_sync(0xffffffffu, sum, m);
    if (lane == 0)
        out[wid] = sum + __ldg(&b2[0]) + __ldg(&b2[1]) + __ldg(&b2[2]);
}

// =====================================================================================
extern "C" void kernel_launch(void* const* d_in, const int* in_sizes, int n_in,
                              void* d_out, int out_size) {
    const float* x  = (const float*)d_in[0];
    const void*  s0 = d_in[1]; const void* d0 = d_in[2];
    const void*  s1 = d_in[3]; const void* d1 = d_in[4];
    const void*  s2 = d_in[5]; const void* d2 = d_in[6];
    const float* W1 = (const float*)d_in[7];
    const float* b1 = (const float*)d_in[8];
    const float* W2 = (const float*)d_in[9];
    const float* b2 = (const float*)d_in[10];
    float* out = (float*)d_out;

    k_init   <<<(NROWS + 255) / 256, 256>>>((const unsigned*)s0);
    k_count  <<<(E_TOT / 2 + 255) / 256, 256>>>(s0, d0, s1, d1, s2, d2);
    k_scan1  <<<NB_SCAN, 256>>>();
    k_scan2  <<<1, 256>>>();
    k_scan3  <<<(NROWS + 255) / 256, 256>>>();
    k_scatter<<<(E_TOT + 255) / 256, 256>>>();           // 6th launch: profiled by -s 5
    k_transform1<<<(NN + 127) / 128, 128>>>(x, W1);
    k_gather1<<<(NN * 32 + 255) / 256, 256>>>(b1, W2);
    k_gather2<<<(NN * 32 + 255) / 256, 256>>>(out, b2);
}

// round 4
// speedup vs baseline: 1.3633x; 1.0023x over previous
#include <cuda_runtime.h>
#include <cuda_fp16.h>
#include <cstdint>

#define NN      50000
#define E_RSR   3000000
#define E_RTR   1000000
#define E_RUR   200000
#define E_TOT   4200000
#define NROWS   (3 * NN)
#define NB_SCAN 147            // ceil(150000 / 1024), must be <= SM count (148)

// ---------------- device scratch ----------------
__device__ int    g_deg_in [NROWS];
__device__ int    g_deg_out[NROWS];
__device__ float  g_rinv_in [NROWS];
__device__ float  g_rinv_out[NROWS];
__device__ int    g_rowptr[NROWS];
__device__ int    g_cursor[NROWS];
__device__ int    g_flag[NB_SCAN];      // published block aggregates (+1)
__device__ int2   g_edge[E_TOT];        // staged (src,dst) int32 pairs
__device__ int    g_ssrc[E_TOT];        // src sorted by (relation, dst)
__device__ __half g_hrh[3][NN * 16];    // fp16 pre-aggregation features
__device__ float  g_gv[NROWS];
__device__ int    g_is64;

// ---------------- helpers ----------------
__device__ __forceinline__ int4 ldcs_i4(const int4* p) {
    int4 v;
    asm volatile("ld.global.cs.v4.b32 {%0,%1,%2,%3}, [%4];"
                 : "=r"(v.x), "=r"(v.y), "=r"(v.z), "=r"(v.w) : "l"(p));
    return v;
}
__device__ __forceinline__ int2 ldcs_i2(const int2* p) {
    int2 v;
    asm volatile("ld.global.cs.v2.b32 {%0,%1}, [%2];" : "=r"(v.x), "=r"(v.y) : "l"(p));
    return v;
}

// ---------------- init: zero counters + flags + dtype probe ----------------
__global__ void k_init(const unsigned* p) {
    int i = blockIdx.x * blockDim.x + threadIdx.x;
    if (i == 0) {
        int all0 = 1;
        #pragma unroll 1
        for (int k = 0; k < 64; k++)
            if (p[2 * k + 1] != 0u) { all0 = 0; break; }
        g_is64 = all0;
    }
    if (i < NROWS) { g_deg_in[i] = 0; g_deg_out[i] = 0; }
    if (i < NB_SCAN) g_flag[i] = 0;
}

// ---------------- convert to int32 + count degrees (2 edges/thread) ----------------
__global__ void k_count(const void* s0, const void* d0,
                        const void* s1, const void* d1,
                        const void* s2, const void* d2) {
    int t = blockIdx.x * blockDim.x + threadIdx.x;
    int i = t * 2;
    if (i >= E_TOT) return;
    int r, e;
    const void *sp, *dp;
    if (i < E_RSR)                { r = 0; e = i;                 sp = s0; dp = d0; }
    else if (i < E_RSR + E_RTR)   { r = 1; e = i - E_RSR;         sp = s1; dp = d1; }
    else                          { r = 2; e = i - E_RSR - E_RTR; sp = s2; dp = d2; }
    int sA, sB, dA, dB;
    if (g_is64) {
        int4 sv = ldcs_i4((const int4*)((const char*)sp + (size_t)e * 8));
        int4 dv = ldcs_i4((const int4*)((const char*)dp + (size_t)e * 8));
        sA = sv.x; sB = sv.z; dA = dv.x; dB = dv.z;
    } else {
        int2 sv = ldcs_i2((const int2*)((const char*)sp + (size_t)e * 4));
        int2 dv = ldcs_i2((const int2*)((const char*)dp + (size_t)e * 4));
        sA = sv.x; sB = sv.y; dA = dv.x; dB = dv.y;
    }
    g_edge[i]     = make_int2(sA, dA);
    g_edge[i + 1] = make_int2(sB, dB);
    int rb = r * NN;
    atomicAdd(&g_deg_out[rb + sA], 1);
    atomicAdd(&g_deg_out[rb + sB], 1);
    atomicAdd(&g_deg_in [rb + dA], 1);
    atomicAdd(&g_deg_in [rb + dB], 1);
}

// ---------------- fused exclusive scan over deg_in (+ rinv, cursor init) ----------------
// 147 blocks x 256 threads x 4 elems. All blocks co-resident: publish-and-poll aggregates.
__global__ void __launch_bounds__(256) k_scan_fused() {
    __shared__ int sd[256];
    __shared__ int s_off;
    int t = threadIdx.x;
    int bid = blockIdx.x;
    int base = bid * 1024 + t * 4;
    int v[4]; int s = 0;
    #pragma unroll
    for (int k = 0; k < 4; k++) {
        int idx = base + k;
        int dv = (idx < NROWS) ? g_deg_in[idx] : 0;
        v[k] = dv; s += dv;
        if (idx < NROWS) {
            g_rinv_in [idx] = rsqrtf(fmaxf((float)dv, 1.f));
            g_rinv_out[idx] = rsqrtf(fmaxf((float)g_deg_out[idx], 1.f));
        }
    }
    sd[t] = s;
    if (t == 0) s_off = 0;
    __syncthreads();
    for (int off = 1; off < 256; off <<= 1) {
        int y = (t >= off) ? sd[t - off] : 0;
        int x = sd[t];
        __syncthreads();
        sd[t] = x + y;
        __syncthreads();
    }
    // publish this block's total (+1 sentinel)
    if (t == 0) {
        int total = sd[255];
        __threadfence();
        atomicExch(&g_flag[bid], total + 1);
    }
    // poll all predecessor aggregates
    if (t < bid) {
        int f;
        do { f = atomicAdd(&g_flag[t], 0); } while (f == 0);
        atomicAdd(&s_off, f - 1);
    }
    __syncthreads();
    int blockoff = s_off;
    int run = blockoff + sd[t] - s;   // exclusive prefix for this thread's 4-group
    #pragma unroll
    for (int k = 0; k < 4; k++) {
        int idx = base + k;
        if (idx < NROWS) { g_rowptr[idx] = run; g_cursor[idx] = run; }
        run += v[k];
    }
}

// ---------------- scatter: counting-sort edge srcs by (relation, dst) ----------------
__global__ void __launch_bounds__(256) k_scatter() {
    int i = blockIdx.x * blockDim.x + threadIdx.x;
    if (i >= E_TOT) return;
    int r = (i >= E_RSR) + (i >= E_RSR + E_RTR);
    int2 ed = g_edge[i];
    int pos = atomicAdd(&g_cursor[r * NN + ed.y], 1);
    g_ssrc[pos] = ed.x;
}

// ---------------- layer-1 transform -> fp16: hr[r][n] = (x[n]*rinv_out) @ W1[r] ----------------
__global__ void k_transform1(const float* __restrict__ x, const float* __restrict__ W1) {
    __shared__ float sW[3 * 32 * 16];
    for (int j = threadIdx.x; j < 1536; j += blockDim.x) sW[j] = W1[j];
    __syncthreads();
    int n = blockIdx.x * blockDim.x + threadIdx.x;
    if (n >= NN) return;
    float xv[32];
    const float4* xp = (const float4*)(x + (size_t)n * 32);
    #pragma unroll
    for (int q = 0; q < 8; q++) {
        float4 v = xp[q];
        xv[4 * q + 0] = v.x; xv[4 * q + 1] = v.y; xv[4 * q + 2] = v.z; xv[4 * q + 3] = v.w;
    }
    #pragma unroll
    for (int r = 0; r < 3; r++) {
        float rv = g_rinv_out[r * NN + n];
        float o[16];
        #pragma unroll
        for (int j = 0; j < 16; j++) o[j] = 0.f;
        #pragma unroll
        for (int k = 0; k < 32; k++) {
            float xk = xv[k];
            const float* w = &sW[r * 512 + k * 16];
            #pragma unroll
            for (int j = 0; j < 16; j++) o[j] = fmaf(xk, w[j], o[j]);
        }
        // pack 16 fp32 -> 8 half2 (16B stores x2)
        uint4* hp = (uint4*)&g_hrh[r][n * 16];
        uint4 pk[2];
        unsigned* pw = (unsigned*)pk;
        #pragma unroll
        for (int q = 0; q < 8; q++) {
            __half2 h = __floats2half2_rn(o[2 * q] * rv, o[2 * q + 1] * rv);
            pw[q] = *(unsigned*)&h;
        }
        hp[0] = pk[0];
        hp[1] = pk[1];
    }
}

// ---------------- gather layer 1 (fused relu + bias + W2 projection) ----------------
// one warp per dst node; lane = slot*4 + chunk; 8 edges x 4 feature-chunks / iter
__global__ void __launch_bounds__(256) k_gather1(const float* __restrict__ b1,
                                                 const float* __restrict__ W2) {
    int wid = (blockIdx.x * blockDim.x + threadIdx.x) >> 5;
    if (wid >= NN) return;
    int lane = threadIdx.x & 31;
    int slot = lane >> 2, chunk = lane & 3;
    float4 acc = make_float4(0.f, 0.f, 0.f, 0.f);
    #pragma unroll
    for (int r = 0; r < 3; r++) {
        int j = r * NN + wid;
        int start = g_rowptr[j];
        int end = (j == NROWS - 1) ? E_TOT : g_rowptr[j + 1];
        float w = g_rinv_in[j];
        for (int base = start; base < end; base += 8) {
            int eid = base + slot;
            if (eid < end) {
                int s = __ldg(&g_ssrc[eid]);
                uint2 u = __ldg((const uint2*)&g_hrh[r][s * 16 + chunk * 4]);
                float2 f0 = __half22float2(*(__half2*)&u.x);
                float2 f1 = __half22float2(*(__half2*)&u.y);
                acc.x = fmaf(f0.x, w, acc.x);
                acc.y = fmaf(f0.y, w, acc.y);
                acc.z = fmaf(f1.x, w, acc.z);
                acc.w = fmaf(f1.y, w, acc.w);
            }
        }
    }
    // reduce across the 8 slots (keep chunk)
    #pragma unroll
    for (int m = 16; m >= 4; m >>= 1) {
        acc.x += __shfl_xor_sync(0xffffffffu, acc.x, m);
        acc.y += __shfl_xor_sync(0xffffffffu, acc.y, m);
        acc.z += __shfl_xor_sync(0xffffffffu, acc.z, m);
        acc.w += __shfl_xor_sync(0xffffffffu, acc.w, m);
    }
    int c4 = chunk * 4;
    #pragma unroll
    for (int k = 0; k < 4; k++) {
        float bs = __ldg(&b1[c4 + k]) + __ldg(&b1[16 + c4 + k]) + __ldg(&b1[32 + c4 + k]);
        float* a = (k == 0) ? &acc.x : (k == 1) ? &acc.y : (k == 2) ? &acc.z : &acc.w;
        *a = fmaxf(*a + bs, 0.f);
    }
    #pragma unroll
    for (int r = 0; r < 3; r++) {
        const float* w2 = W2 + r * 16 + c4;
        float p = acc.x * __ldg(&w2[0]) + acc.y * __ldg(&w2[1])
                + acc.z * __ldg(&w2[2]) + acc.w * __ldg(&w2[3]);
        p += __shfl_xor_sync(0xffffffffu, p, 1);
        p += __shfl_xor_sync(0xffffffffu, p, 2);
        if (lane == r) g_gv[r * NN + wid] = p * g_rinv_out[r * NN + wid];
    }
}

// ---------------- gather layer 2: out[dst] = sum_r sum_e gv[r][src]*rinv_in + b2s ----------------
__global__ void __launch_bounds__(256) k_gather2(float* __restrict__ out,
                                                 const float* __restrict__ b2) {
    int wid = (blockIdx.x * blockDim.x + threadIdx.x) >> 5;
    if (wid >= NN) return;
    int lane = threadIdx.x & 31;
    float sum = 0.f;
    #pragma unroll
    for (int r = 0; r < 3; r++) {
        int j = r * NN + wid;
        int start = g_rowptr[j];
        int end = (j == NROWS - 1) ? E_TOT : g_rowptr[j + 1];
        float w = g_rinv_in[j];
        for (int base = start; base < end; base += 32) {
            int eid = base + lane;
            if (eid < end) {
                int s = __ldg(&g_ssrc[eid]);
                sum = fmaf(__ldg(&g_gv[r * NN + s]), w, sum);
            }
        }
    }
    #pragma unroll
    for (int m = 16; m >= 1; m >>= 1)
        sum += __shfl_xor_sync(0xffffffffu, sum, m);
    if (lane == 0)
        out[wid] = sum + __ldg(&b2[0]) + __ldg(&b2[1]) + __ldg(&b2[2]);
}

// =====================================================================================
extern "C" void kernel_launch(void* const* d_in, const int* in_sizes, int n_in,
                              void* d_out, int out_size) {
    const float* x  = (const float*)d_in[0];
    const void*  s0 = d_in[1]; const void* d0 = d_in[2];
    const void*  s1 = d_in[3]; const void* d1 = d_in[4];
    const void*  s2 = d_in[5]; const void* d2 = d_in[6];
    const float* W1 = (const float*)d_in[7];
    const float* b1 = (const float*)d_in[8];
    const float* W2 = (const float*)d_in[9];
    const float* b2 = (const float*)d_in[10];
    float* out = (float*)d_out;

    k_init      <<<(NROWS + 255) / 256, 256>>>((const unsigned*)s0);        // 0
    k_count     <<<(E_TOT / 2 + 255) / 256, 256>>>(s0, d0, s1, d1, s2, d2); // 1
    k_scan_fused<<<NB_SCAN, 256>>>();                                       // 2
    k_scatter   <<<(E_TOT + 255) / 256, 256>>>();                           // 3
    k_transform1<<<(NN + 127) / 128, 128>>>(x, W1);                         // 4
    k_gather1   <<<(NN * 32 + 255) / 256, 256>>>(b1, W2);                   // 5  <- profiled
    k_gather2   <<<(NN * 32 + 255) / 256, 256>>>(out, b2);                  // 6
}

// round 5
// speedup vs baseline: 1.3920x; 1.0210x over previous
#include <cuda_runtime.h>
#include <cuda_fp16.h>
#include <cstdint>

#define NN      50000
#define E_RSR   3000000
#define E_RTR   1000000
#define E_RUR   200000
#define E_TOT   4200000
#define NROWS   (3 * NN)
#define NB_SCAN 147            // ceil(150000 / 1024), <= SM count (148)

// ---------------- device scratch ----------------
__device__ int    g_deg_in [NROWS];
__device__ int    g_deg_out[NROWS];
__device__ float  g_rinv_in [NROWS];
__device__ int    g_rowptr[NROWS];
__device__ int    g_cursor[NROWS];
__device__ int    g_flag[NB_SCAN];
__device__ int    g_ssrc[E_TOT];        // src sorted by (relation, dst)
__device__ __half g_hrh[3][NN * 16];    // fp16 pre-aggregation features
__device__ float  g_gv[NROWS];
__device__ int    g_is64;

// ---------------- helpers ----------------
__device__ __forceinline__ int4 ldcs_i4(const void* p) {
    int4 v;
    asm volatile("ld.global.cs.v4.b32 {%0,%1,%2,%3}, [%4];"
                 : "=r"(v.x), "=r"(v.y), "=r"(v.z), "=r"(v.w) : "l"(p));
    return v;
}
__device__ __forceinline__ int2 ldcs_i2(const void* p) {
    int2 v;
    asm volatile("ld.global.cs.v2.b32 {%0,%1}, [%2];" : "=r"(v.x), "=r"(v.y) : "l"(p));
    return v;
}
__device__ __forceinline__ float rinv_of(int deg) {
    return rsqrtf(fmaxf((float)deg, 1.f));
}

// ---------------- init: zero counters + flags + dtype probe ----------------
__global__ void k_init(const unsigned* p) {
    int i = blockIdx.x * blockDim.x + threadIdx.x;
    if (i == 0) {
        int all0 = 1;
        #pragma unroll 1
        for (int k = 0; k < 64; k++)
            if (p[2 * k + 1] != 0u) { all0 = 0; break; }
        g_is64 = all0;
    }
    if (i < NROWS) { g_deg_in[i] = 0; g_deg_out[i] = 0; }
    if (i < NB_SCAN) g_flag[i] = 0;
}

// ---------------- count degrees only (4 edges/thread, no staging) ----------------
__global__ void __launch_bounds__(256) k_count(const void* s0, const void* d0,
                                               const void* s1, const void* d1,
                                               const void* s2, const void* d2) {
    int t = blockIdx.x * blockDim.x + threadIdx.x;
    int i = t * 4;                       // first edge handled by this thread
    if (i >= E_TOT) return;
    int r, e;
    const void *sp, *dp;
    if (i < E_RSR)                { r = 0; e = i;                 sp = s0; dp = d0; }
    else if (i < E_RSR + E_RTR)   { r = 1; e = i - E_RSR;         sp = s1; dp = d1; }
    else                          { r = 2; e = i - E_RSR - E_RTR; sp = s2; dp = d2; }
    // relation sizes divisible by 4 -> a 4-group never straddles relations
    int s[4], d[4];
    if (g_is64) {
        int4 a = ldcs_i4((const char*)sp + (size_t)e * 8);
        int4 b = ldcs_i4((const char*)sp + (size_t)e * 8 + 16);
        s[0] = a.x; s[1] = a.z; s[2] = b.x; s[3] = b.z;
        int4 c = ldcs_i4((const char*)dp + (size_t)e * 8);
        int4 f = ldcs_i4((const char*)dp + (size_t)e * 8 + 16);
        d[0] = c.x; d[1] = c.z; d[2] = f.x; d[3] = f.z;
    } else {
        int4 a = ldcs_i4((const char*)sp + (size_t)e * 4);
        s[0] = a.x; s[1] = a.y; s[2] = a.z; s[3] = a.w;
        int4 c = ldcs_i4((const char*)dp + (size_t)e * 4);
        d[0] = c.x; d[1] = c.y; d[2] = c.z; d[3] = c.w;
    }
    int rb = r * NN;
    #pragma unroll
    for (int k = 0; k < 4; k++) {
        atomicAdd(&g_deg_out[rb + s[k]], 1);   // no return use -> RED
        atomicAdd(&g_deg_in [rb + d[k]], 1);
    }
}

// ---------------- fused exclusive scan over deg_in (+ rinv_in, cursor init) ----------------
__global__ void __launch_bounds__(256) k_scan_fused() {
    __shared__ int sd[256];
    __shared__ int s_off;
    int t = threadIdx.x;
    int bid = blockIdx.x;
    int base = bid * 1024 + t * 4;
    int v[4]; int s = 0;
    #pragma unroll
    for (int k = 0; k < 4; k++) {
        int idx = base + k;
        int dv = (idx < NROWS) ? g_deg_in[idx] : 0;
        v[k] = dv; s += dv;
        if (idx < NROWS) g_rinv_in[idx] = rinv_of(dv);
    }
    sd[t] = s;
    if (t == 0) s_off = 0;
    __syncthreads();
    for (int off = 1; off < 256; off <<= 1) {
        int y = (t >= off) ? sd[t - off] : 0;
        int x = sd[t];
        __syncthreads();
        sd[t] = x + y;
        __syncthreads();
    }
    if (t == 0) {
        int total = sd[255];
        __threadfence();
        atomicExch(&g_flag[bid], total + 1);
    }
    if (t < bid) {
        int f;
        do { f = atomicAdd(&g_flag[t], 0); } while (f == 0);
        atomicAdd(&s_off, f - 1);
    }
    __syncthreads();
    int run = s_off + sd[t] - s;
    #pragma unroll
    for (int k = 0; k < 4; k++) {
        int idx = base + k;
        if (idx < NROWS) { g_rowptr[idx] = run; g_cursor[idx] = run; }
        run += v[k];
    }
}

// ---------------- scatter: counting-sort srcs by (relation,dst), 2 edges/thread ----------------
__global__ void __launch_bounds__(256) k_scatter(const void* s0, const void* d0,
                                                 const void* s1, const void* d1,
                                                 const void* s2, const void* d2) {
    int t = blockIdx.x * blockDim.x + threadIdx.x;
    int i = t * 2;
    if (i >= E_TOT) return;
    int r, e;
    const void *sp, *dp;
    if (i < E_RSR)                { r = 0; e = i;                 sp = s0; dp = d0; }
    else if (i < E_RSR + E_RTR)   { r = 1; e = i - E_RSR;         sp = s1; dp = d1; }
    else                          { r = 2; e = i - E_RSR - E_RTR; sp = s2; dp = d2; }
    int sA, sB, dA, dB;
    if (g_is64) {
        int4 sv = ldcs_i4((const char*)sp + (size_t)e * 8);
        int4 dv = ldcs_i4((const char*)dp + (size_t)e * 8);
        sA = sv.x; sB = sv.z; dA = dv.x; dB = dv.z;
    } else {
        int2 sv = ldcs_i2((const char*)sp + (size_t)e * 4);
        int2 dv = ldcs_i2((const char*)dp + (size_t)e * 4);
        sA = sv.x; sB = sv.y; dA = dv.x; dB = dv.y;
    }
    int rb = r * NN;
    int pA = atomicAdd(&g_cursor[rb + dA], 1);
    g_ssrc[pA] = sA;
    int pB = atomicAdd(&g_cursor[rb + dB], 1);
    g_ssrc[pB] = sB;
}

// ---------------- layer-1 transform -> fp16 ----------------
__global__ void k_transform1(const float* __restrict__ x, const float* __restrict__ W1) {
    __shared__ float sW[3 * 32 * 16];
    for (int j = threadIdx.x; j < 1536; j += blockDim.x) sW[j] = W1[j];
    __syncthreads();
    int n = blockIdx.x * blockDim.x + threadIdx.x;
    if (n >= NN) return;
    float xv[32];
    const float4* xp = (const float4*)(x + (size_t)n * 32);
    #pragma unroll
    for (int q = 0; q < 8; q++) {
        float4 v = xp[q];
        xv[4 * q + 0] = v.x; xv[4 * q + 1] = v.y; xv[4 * q + 2] = v.z; xv[4 * q + 3] = v.w;
    }
    #pragma unroll
    for (int r = 0; r < 3; r++) {
        float rv = rinv_of(g_deg_out[r * NN + n]);
        float o[16];
        #pragma unroll
        for (int j = 0; j < 16; j++) o[j] = 0.f;
        #pragma unroll
        for (int k = 0; k < 32; k++) {
            float xk = xv[k];
            const float* w = &sW[r * 512 + k * 16];
            #pragma unroll
            for (int j = 0; j < 16; j++) o[j] = fmaf(xk, w[j], o[j]);
        }
        uint4* hp = (uint4*)&g_hrh[r][n * 16];
        uint4 pk[2];
        unsigned* pw = (unsigned*)pk;
        #pragma unroll
        for (int q = 0; q < 8; q++) {
            __half2 h = __floats2half2_rn(o[2 * q] * rv, o[2 * q + 1] * rv);
            pw[q] = *(unsigned*)&h;
        }
        hp[0] = pk[0];
        hp[1] = pk[1];
    }
}

// ---------------- gather layer 1 (fused relu + bias + W2 projection) ----------------
__global__ void __launch_bounds__(256) k_gather1(const float* __restrict__ b1,
                                                 const float* __restrict__ W2) {
    int wid = (blockIdx.x * blockDim.x + threadIdx.x) >> 5;
    if (wid >= NN) return;
    int lane = threadIdx.x & 31;
    int slot = lane >> 2, chunk = lane & 3;
    float4 acc = make_float4(0.f, 0.f, 0.f, 0.f);
    #pragma unroll
    for (int r = 0; r < 3; r++) {
        int j = r * NN + wid;
        int start = g_rowptr[j];
        int end = g_cursor[j];              // cursor == end after scatter
        float w = g_rinv_in[j];
        for (int base = start; base < end; base += 8) {
            int eid = base + slot;
            if (eid < end) {
                int s = __ldg(&g_ssrc[eid]);
                uint2 u = __ldg((const uint2*)&g_hrh[r][s * 16 + chunk * 4]);
                float2 f0 = __half22float2(*(__half2*)&u.x);
                float2 f1 = __half22float2(*(__half2*)&u.y);
                acc.x = fmaf(f0.x, w, acc.x);
                acc.y = fmaf(f0.y, w, acc.y);
                acc.z = fmaf(f1.x, w, acc.z);
                acc.w = fmaf(f1.y, w, acc.w);
            }
        }
    }
    #pragma unroll
    for (int m = 16; m >= 4; m >>= 1) {
        acc.x += __shfl_xor_sync(0xffffffffu, acc.x, m);
        acc.y += __shfl_xor_sync(0xffffffffu, acc.y, m);
        acc.z += __shfl_xor_sync(0xffffffffu, acc.z, m);
        acc.w += __shfl_xor_sync(0xffffffffu, acc.w, m);
    }
    int c4 = chunk * 4;
    #pragma unroll
    for (int k = 0; k < 4; k++) {
        float bs = __ldg(&b1[c4 + k]) + __ldg(&b1[16 + c4 + k]) + __ldg(&b1[32 + c4 + k]);
        float* a = (k == 0) ? &acc.x : (k == 1) ? &acc.y : (k == 2) ? &acc.z : &acc.w;
        *a = fmaxf(*a + bs, 0.f);
    }
    #pragma unroll
    for (int r = 0; r < 3; r++) {
        const float* w2 = W2 + r * 16 + c4;
        float p = acc.x * __ldg(&w2[0]) + acc.y * __ldg(&w2[1])
                + acc.z * __ldg(&w2[2]) + acc.w * __ldg(&w2[3]);
        p += __shfl_xor_sync(0xffffffffu, p, 1);
        p += __shfl_xor_sync(0xffffffffu, p, 2);
        if (lane == r)
            g_gv[r * NN + wid] = p * rinv_of(__ldg(&g_deg_out[r * NN + wid]));
    }
}

// ---------------- gather layer 2 ----------------
__global__ void __launch_bounds__(256) k_gather2(float* __restrict__ out,
                                                 const float* __restrict__ b2) {
    int wid = (blockIdx.x * blockDim.x + threadIdx.x) >> 5;
    if (wid >= NN) return;
    int lane = threadIdx.x & 31;
    float sum = 0.f;
    #pragma unroll
    for (int r = 0; r < 3; r++) {
        int j = r * NN + wid;
        int start = g_rowptr[j];
        int end = g_cursor[j];
        float w = g_rinv_in[j];
        for (int base = start; base < end; base += 32) {
            int eid = base + lane;
            if (eid < end) {
                int s = __ldg(&g_ssrc[eid]);
                sum = fmaf(__ldg(&g_gv[r * NN + s]), w, sum);
            }
        }
    }
    #pragma unroll
    for (int m = 16; m >= 1; m >>= 1)
        sum += __shfl_xor_sync(0xffffffffu, sum, m);
    if (lane == 0)
        out[wid] = sum + __ldg(&b2[0]) + __ldg(&b2[1]) + __ldg(&b2[2]);
}

// =====================================================================================
extern "C" void kernel_launch(void* const* d_in, const int* in_sizes, int n_in,
                              void* d_out, int out_size) {
    const float* x  = (const float*)d_in[0];
    const void*  s0 = d_in[1]; const void* d0 = d_in[2];
    const void*  s1 = d_in[3]; const void* d1 = d_in[4];
    const void*  s2 = d_in[5]; const void* d2 = d_in[6];
    const float* W1 = (const float*)d_in[7];
    const float* b1 = (const float*)d_in[8];
    const float* W2 = (const float*)d_in[9];
    const float* b2 = (const float*)d_in[10];
    float* out = (float*)d_out;

    k_init      <<<(NROWS + 255) / 256, 256>>>((const unsigned*)s0);
    k_count     <<<(E_TOT / 4 + 255) / 256, 256>>>(s0, d0, s1, d1, s2, d2);
    k_scan_fused<<<NB_SCAN, 256>>>();
    k_scatter   <<<(E_TOT / 2 + 255) / 256, 256>>>(s0, d0, s1, d1, s2, d2);
    k_transform1<<<(NN + 127) / 128, 128>>>(x, W1);
    k_gather1   <<<(NN * 32 + 255) / 256, 256>>>(b1, W2);
    k_gather2   <<<(NN * 32 + 255) / 256, 256>>>(out, b2);
}